// round 14
// baseline (speedup 1.0000x reference)
#include <cuda_runtime.h>

// Linear-chain CRF NLL: fused forward (log-partition) + gold score.
// B=4096, L=1024, T=32. ONE batch per 32-thread warp-block -> 4096 warps.
// ZERO shared memory, ZERO __syncthreads in the hot loop: fv state lives in
// registers (lane t holds v[t]); each step, lane l=r+8c gathers its 8-prev
// chunk via 8 SHFL.IDX, packs even/odd prev pairs as f32x2, runs 16 fma2
// over 4 row-slots (rows r+8*(c^s)), reduce-scatters with shfl_xor 16 / 8,
// folds parity, multiplies by exp(feat). Exact power-of-2 renorm every 4
// steps via __reduce_max_sync. Emission gold fused in-loop; transition gold
// in a bulk gather phase after the loop. 2-buffer feat prefetch (4-step lead).

namespace {

constexpr int T_ = 32;
constexpr int L_ = 1024;
constexpr int START_ = 30;
constexpr int STOP_ = 31;
constexpr unsigned FULL_ = 0xffffffffu;
typedef unsigned long long u64;

__device__ __forceinline__ u64 pack2(float lo, float hi) {
    u64 r;
    asm("mov.b64 %0, {%1, %2};" : "=l"(r) : "f"(lo), "f"(hi));
    return r;
}
__device__ __forceinline__ void unpack2(u64 v, float& lo, float& hi) {
    asm("mov.b64 {%0, %1}, %2;" : "=f"(lo), "=f"(hi) : "l"(v));
}
__device__ __forceinline__ void fma2(u64& acc, u64 a, u64 b) {
    asm("fma.rn.f32x2 %0, %1, %2, %0;" : "+l"(acc) : "l"(a), "l"(b));
}
__device__ __forceinline__ u64 add2(u64 a, u64 b) {
    u64 r;
    asm("add.rn.f32x2 %0, %1, %2;" : "=l"(r) : "l"(a), "l"(b));
    return r;
}

template <int TS>
__device__ __forceinline__ void crf_body(const float* __restrict__ feats,
                                         const float* __restrict__ trans,
                                         const unsigned* __restrict__ tagw,
                                         float* __restrict__ out) {
    const int t = threadIdx.x;
    const int r = t & 7;
    const int c = t >> 3;
    const int b = blockIdx.x;

    // E2[s][m] = {exp(trans[row_s][8c+2m]), exp(trans[row_s][8c+2m+1])},
    // row_s = r + 8*(c^s). 16 u64 = 32 regs.
    u64 E2[4][4];
#pragma unroll
    for (int s = 0; s < 4; ++s) {
        const float* tr = trans + (r + 8 * (c ^ s)) * T_ + 8 * c;
#pragma unroll
        for (int m = 0; m < 4; ++m)
            E2[s][m] = pack2(__expf(__ldg(tr + 2 * m)), __expf(__ldg(tr + 2 * m + 1)));
    }

    // fv in registers: lane t owns state t. Init: v[START]=1, else 0.
    float v = (t == START_) ? 1.0f : 0.0f;

    const float* fb = feats + (size_t)b * L_ * T_ + t;
    const unsigned* tb = tagw + (size_t)b * L_ * TS;

    float F[2][4];   // feat prefetch [buf][step]
    unsigned P[2];   // 4 tags byte-packed per buf
    int sc = 0;      // log2 scale accumulator
    float ge = 0.f;  // gold emission partial (this lane's state)

#define PF(I, G)                                                               \
    do {                                                                       \
        const int gc_ = ((G) < 256) ? (G) : 255;                               \
        const float* q_ = fb + gc_ * 128;                                      \
        _Pragma("unroll") for (int s_ = 0; s_ < 4; ++s_)                       \
            F[I][s_] = __ldg(q_ + s_ * 32);                                    \
        if (TS == 1) {                                                         \
            uint4 w_ = __ldg((const uint4*)(tb + gc_ * 4));                    \
            P[I] = w_.x | (w_.y << 8) | (w_.z << 16) | (w_.w << 24);           \
        } else {                                                               \
            uint4 a_ = __ldg((const uint4*)(tb + gc_ * 8));                    \
            uint4 c_ = __ldg((const uint4*)(tb + gc_ * 8 + 4));                \
            P[I] = a_.x | (a_.z << 8) | (c_.x << 16) | (c_.z << 24);           \
        }                                                                      \
    } while (0)

#define STEP(I, S, RN)                                                         \
    do {                                                                       \
        const float f_ = F[I][S];                                              \
        /* gather my chunk's 8 prev values straight from lane registers */     \
        const float g0_ = __shfl_sync(FULL_, v, 8 * c + 0);                    \
        const float g1_ = __shfl_sync(FULL_, v, 8 * c + 1);                    \
        const float g2_ = __shfl_sync(FULL_, v, 8 * c + 2);                    \
        const float g3_ = __shfl_sync(FULL_, v, 8 * c + 3);                    \
        const float g4_ = __shfl_sync(FULL_, v, 8 * c + 4);                    \
        const float g5_ = __shfl_sync(FULL_, v, 8 * c + 5);                    \
        const float g6_ = __shfl_sync(FULL_, v, 8 * c + 6);                    \
        const float g7_ = __shfl_sync(FULL_, v, 8 * c + 7);                    \
        const u64 w0_ = pack2(g0_, g1_);                                       \
        const u64 w1_ = pack2(g2_, g3_);                                       \
        const u64 w2_ = pack2(g4_, g5_);                                       \
        const u64 w3_ = pack2(g6_, g7_);                                       \
        u64 a0_ = 0ULL, a1_ = 0ULL, a2_ = 0ULL, a3_ = 0ULL;                    \
        fma2(a0_, w0_, E2[0][0]); fma2(a1_, w0_, E2[1][0]);                    \
        fma2(a2_, w0_, E2[2][0]); fma2(a3_, w0_, E2[3][0]);                    \
        fma2(a0_, w1_, E2[0][1]); fma2(a1_, w1_, E2[1][1]);                    \
        fma2(a2_, w1_, E2[2][1]); fma2(a3_, w1_, E2[3][1]);                    \
        fma2(a0_, w2_, E2[0][2]); fma2(a1_, w2_, E2[1][2]);                    \
        fma2(a2_, w2_, E2[2][2]); fma2(a3_, w2_, E2[3][2]);                    \
        fma2(a0_, w3_, E2[0][3]); fma2(a1_, w3_, E2[1][3]);                    \
        fma2(a2_, w3_, E2[2][3]); fma2(a3_, w3_, E2[3][3]);                    \
        /* reduce-scatter: xor16 merges chunk c^2, xor8 merges c^1 (+c^3) */   \
        a0_ = add2(a0_, __shfl_xor_sync(FULL_, a2_, 16));                      \
        a1_ = add2(a1_, __shfl_xor_sync(FULL_, a3_, 16));                      \
        a0_ = add2(a0_, __shfl_xor_sync(FULL_, a1_, 8));                       \
        float lo_, hi_;                                                        \
        unpack2(a0_, lo_, hi_);                                                \
        v = (lo_ + hi_) * __expf(f_);                                          \
        if (RN) {                                                              \
            unsigned m_ = __reduce_max_sync(FULL_, __float_as_uint(v));        \
            int e_ = (int)(m_ >> 23) - 127;                                    \
            e_ = max(-64, min(e_, 120));                                       \
            v *= __uint_as_float((unsigned)(127 - e_) << 23);                  \
            sc += e_;                                                          \
        }                                                                      \
        const unsigned gt_ = (P[I] >> (8 * (S))) & 0xffu;                      \
        ge += (t == (int)gt_) ? f_ : 0.0f;                                     \
    } while (0)

#define GROUP(I)                                                               \
    do {                                                                       \
        STEP(I, 0, false);                                                     \
        STEP(I, 1, false);                                                     \
        STEP(I, 2, false);                                                     \
        STEP(I, 3, true);                                                      \
    } while (0)

    // Prologue: fill both prefetch buffers (groups 0 and 1).
    PF(0, 0);
    PF(1, 1);

    // 256 groups of 4 steps; refill each buffer right after consuming it
    // (one-group = 4-step lead, ~1200 cyc >> DRAM latency).
#pragma unroll 1
    for (int g2 = 0; g2 < 128; ++g2) {
        GROUP(0);
        PF(0, 2 * g2 + 2);
        GROUP(1);
        PF(1, 2 * g2 + 3);
    }

#undef PF
#undef STEP
#undef GROUP

    // ---- bulk gold transition score: sum_l trans[g_l, g_{l-1}] (+STOP term).
    float gt = 0.f;
    {
        unsigned carry = START_;
#pragma unroll 4
        for (int it = 0; it < 32; ++it) {
            const int l = it * 32 + t;
            unsigned g = (TS == 1) ? __ldg(tb + l) : __ldg(tb + 2 * l);
            unsigned prev = __shfl_up_sync(FULL_, g, 1);
            if (t == 0) prev = carry;
            carry = __shfl_sync(FULL_, g, 31);
            gt += __ldg(trans + g * 32u + prev);
        }
        if (t == 0) gt += __ldg(trans + STOP_ * 32u + carry);
    }

    // ---- epilogue: alpha = log( sum_t v[t]*exp(trans[STOP,t]) ) + sc*ln2 ----
    float z = v * __expf(__ldg(trans + STOP_ * T_ + t));
    float gold = ge + gt;
#pragma unroll
    for (int o = 16; o > 0; o >>= 1) {
        z += __shfl_xor_sync(FULL_, z, o);
        gold += __shfl_xor_sync(FULL_, gold, o);
    }

    if (t == 0) {
        const float LN2 = 0.6931471805599453f;
        out[b] = __logf(z) + (float)sc * LN2 - gold;
    }
}

__global__ void __launch_bounds__(32, 28) crf_fwd(const float* __restrict__ feats,
                                                  const float* __restrict__ trans,
                                                  const unsigned* __restrict__ tagw,
                                                  float* __restrict__ out) {
    // Tag dtype detection: int64 tags (values < 30) have all-zero odd words.
    unsigned oddw = __ldg(tagw + 2 * threadIdx.x + 1);
    if (__any_sync(FULL_, oddw != 0)) {
        crf_body<1>(feats, trans, tagw, out);  // int32 tags
    } else {
        crf_body<2>(feats, trans, tagw, out);  // int64 tags
    }
}

}  // namespace

extern "C" void kernel_launch(void* const* d_in, const int* in_sizes, int n_in,
                              void* d_out, int out_size) {
    const float* feats = (const float*)d_in[0];
    const float* trans = (const float*)d_in[1];
    const unsigned* tagw = (const unsigned*)d_in[2];
    float* out = (float*)d_out;

    const int B = in_sizes[2] / L_;  // element count = B*L for either tag dtype
    crf_fwd<<<B, 32>>>(feats, trans, tagw, out);
}